// round 13
// baseline (speedup 1.0000x reference)
#include <cuda_runtime.h>
#include <cuda_fp16.h>
#include <math.h>
#include <stdint.h>

#define BS   8192           // B*S
#define SEQ  1024
#define NB   8
#define NH   4
#define DMODEL 768
#define DV   192            // per-head V dim

// ---------------- scratch (static device memory; no allocations) -------------
__device__ __half   g_qh[BS * 32];
__device__ __half   g_kh[BS * 32];
__device__ float    g_posr[BS * DMODEL];              // tf32-rounded position
__device__ uint32_t g_vt[NB * NH * 192 * 512];        // V^T half2: [bh][d][i/2]
__device__ float    g_att[BS * DMODEL];
__device__ float    g_pam[BS * DMODEL];
__device__ float    g_posp[BS * DMODEL];
__device__ float    g_wpt[DMODEL * DMODEL];           // Wpam^T (tf32-rounded)
__device__ float    g_wmt[DMODEL * 2 * DMODEL];       // Wm^T   (tf32-rounded)

// ---------------- helpers ----------------------------------------------------
__device__ __forceinline__ uint32_t smem_u32(const void* p) {
    uint32_t a;
    asm("{ .reg .u64 t; cvta.to.shared.u64 t, %1; cvt.u32.u64 %0, t; }"
        : "=r"(a) : "l"(p));
    return a;
}
__device__ __forceinline__ float rna(float f) {
    uint32_t r;
    asm("cvt.rna.tf32.f32 %0, %1;" : "=r"(r) : "f"(f));
    return __uint_as_float(r);
}
__device__ __forceinline__ void mma_tf32(float c[4], const uint32_t a[4],
                                         const uint32_t b[2]) {
    asm volatile("mma.sync.aligned.m16n8k8.row.col.f32.tf32.tf32.f32 "
                 "{%0,%1,%2,%3}, {%4,%5,%6,%7}, {%8,%9}, {%0,%1,%2,%3};"
                 : "+f"(c[0]), "+f"(c[1]), "+f"(c[2]), "+f"(c[3])
                 : "r"(a[0]), "r"(a[1]), "r"(a[2]), "r"(a[3]),
                   "r"(b[0]), "r"(b[1]));
}
__device__ __forceinline__ void mma_f16(float c[4],
                                        uint32_t a0, uint32_t a1,
                                        uint32_t a2, uint32_t a3,
                                        uint32_t b0, uint32_t b1) {
    asm volatile("mma.sync.aligned.m16n8k16.row.col.f32.f16.f16.f32 "
                 "{%0,%1,%2,%3}, {%4,%5,%6,%7}, {%8,%9}, {%0,%1,%2,%3};"
                 : "+f"(c[0]), "+f"(c[1]), "+f"(c[2]), "+f"(c[3])
                 : "r"(a0), "r"(a1), "r"(a2), "r"(a3), "r"(b0), "r"(b1));
}
__device__ __forceinline__ uint32_t pack2h(float a, float b) {
    __half ha = __float2half_rn(a), hb = __float2half_rn(b);
    return (uint32_t)__half_as_ushort(ha) | ((uint32_t)__half_as_ushort(hb) << 16);
}
#define CP_ASYNC16(saddr, gptr) \
    asm volatile("cp.async.cg.shared.global [%0], [%1], 16;" \
                 :: "r"(saddr), "l"(gptr))
#define CP_ASYNC4(saddr, gptr) \
    asm volatile("cp.async.ca.shared.global [%0], [%1], 4;" \
                 :: "r"(saddr), "l"(gptr))
#define CP_COMMIT() asm volatile("cp.async.commit_group;")
#define CP_WAIT0()  asm volatile("cp.async.wait_group 0;")
#define CP_WAIT1()  asm volatile("cp.async.wait_group 1;")

// ---------------- prep kernels ------------------------------------------------
__global__ __launch_bounds__(256)
void prep_pos(const float* __restrict__ pos, float* __restrict__ out)
{
    const int idx = blockIdx.x * 256 + threadIdx.x;
    const float4 v = *(const float4*)(pos + (size_t)idx * 4);
    float4 o;
    o.x = rna(v.x); o.y = rna(v.y); o.z = rna(v.z); o.w = rna(v.w);
    *(float4*)(out + (size_t)idx * 4) = o;
}

// V^T prep: g_vt[(b*NH+h)*192+d][m] = half2(x[b][2m][h*192+d], x[b][2m+1][..])
__global__ __launch_bounds__(256)
void prep_vt(const float* __restrict__ x, uint32_t* __restrict__ vt)
{
    __shared__ float t[64][33];
    const int s0 = blockIdx.x * 64, c0 = blockIdx.y * 32, b = blockIdx.z;
    const int tid = threadIdx.x;
#pragma unroll
    for (int i = 0; i < 8; ++i) {
        const int idx = tid + i * 256;
        const int r = idx >> 5, cc = idx & 31;
        t[r][cc] = x[((size_t)b * SEQ + s0 + r) * DMODEL + c0 + cc];
    }
    __syncthreads();
#pragma unroll
    for (int i = 0; i < 4; ++i) {
        const int idx = tid + i * 256;
        const int cc = idx >> 5, m = idx & 31;
        const int c = c0 + cc, h = c / 192, d = c % 192;
        vt[((size_t)(b * NH + h) * 192 + d) * 512 + s0 / 2 + m]
            = pack2h(t[2 * m][cc], t[2 * m + 1][cc]);
    }
}

// weight transpose W[K][N] -> WT[N][K], tf32-rounded
__global__ __launch_bounds__(256)
void transpose_k(const float* __restrict__ W, float* __restrict__ WT, int K, int N)
{
    __shared__ float t[32][33];
    const int k0 = blockIdx.y * 32, n0 = blockIdx.x * 32;
    const int tx = threadIdx.x & 31, ty = threadIdx.x >> 5;
#pragma unroll
    for (int r = ty; r < 32; r += 8)
        t[r][tx] = W[(size_t)(k0 + r) * N + n0 + tx];
    __syncthreads();
#pragma unroll
    for (int r = ty; r < 32; r += 8)
        WT[(size_t)(n0 + r) * K + k0 + tx] = rna(t[tx][r]);
}

// ---------------- q/k projection + ReLU -> fp16 -------------------------------
__global__ __launch_bounds__(256)
void qk_proj(const float* __restrict__ x,
             const float* __restrict__ Wq, const float* __restrict__ bq,
             const float* __restrict__ Wk, const float* __restrict__ bk,
             __half* __restrict__ q, __half* __restrict__ k)
{
    const int row  = (blockIdx.x * blockDim.x + threadIdx.x) >> 5;
    const int lane = threadIdx.x & 31;
    if (row >= BS) return;
    const float* xr = x + (size_t)row * DMODEL;
    float aq = bq[lane];
    float ak = bk[lane];
#pragma unroll 8
    for (int d = 0; d < DMODEL; ++d) {
        const float xv = __ldg(xr + d);
        aq = fmaf(xv, __ldg(Wq + d * 32 + lane), aq);
        ak = fmaf(xv, __ldg(Wk + d * 32 + lane), ak);
    }
    q[(size_t)row * 32 + lane] = __float2half_rn(fmaxf(aq, 0.f));
    k[(size_t)row * 32 + lane] = __float2half_rn(fmaxf(ak, 0.f));
}

// ---------------- flash attention, cp.async pipelined --------------------------
// out[j] = sum_i softmax_i( Q[j]·K[i]*scale, masked ) * V[i]   (transpose trick)
// PAM=true : Q/K = tf32 fp32 rows of 192 (g_posr); QK^T via m16n8k8 tf32.
// PAM=false: Q/K = fp16 rows of 8 (g_kh/g_qh);    QK^T via one m16n8k16 fp16.
// PV: fp16 m16n8k16 from pre-transposed g_vt. 3 barriers/iter, double-buffered.
template<bool PAM>
__global__ __launch_bounds__(256)
void flash2(const float* __restrict__ Qf, const float* __restrict__ Kf,
            const __half* __restrict__ Qh, const __half* __restrict__ Kh,
            const uint32_t* __restrict__ Vt, const int* __restrict__ mask,
            float* __restrict__ Og, float scale)
{
    constexpr int LDK = PAM ? 196 : 12;       // u32 row stride (=4 mod 32)
    constexpr int OQ  = 0;
    constexpr int OK0 = OQ  + 64 * LDK;
    constexpr int OK1 = OK0 + 64 * LDK;
    constexpr int OV0 = OK1 + 64 * LDK;
    constexpr int OV1 = OV0 + 192 * 36;
    constexpr int OP  = OV1 + 192 * 36;
    constexpr int ORM = OP  + 64 * 36;
    constexpr int ORS = ORM + 128;
    constexpr int OMX = ORS + 128;            // [2][64]
    constexpr int OLX = OMX + 128;            // [2][64]
    constexpr int OMI = OLX + 128;            // [2][64] int

    extern __shared__ __align__(16) uint32_t sm[];
    float* fsm = (float*)sm;
    int*   ism = (int*)sm;
    const uint32_t sb = smem_u32(sm);

    const int tid = threadIdx.x;
    const int wid = tid >> 5, lane = tid & 31;
    const int g = lane >> 2, t = lane & 3;
    const int mw = wid >> 1, nw = wid & 1;
    const int r0 = mw * 16 + g, r1 = r0 + 8;
    const int qt = blockIdx.x, h = blockIdx.y, b = blockIdx.z;
    const int j0 = qt * 64;
    const long brow = (long)b * SEQ;
    const int bh = b * NH + h;

    // --- issue Q tile loads ---
    if (PAM) {
#pragma unroll
        for (int i = 0; i < 12; ++i) {
            const int idx = tid + i * 256;
            const int r = idx / 48, c = idx % 48;
            CP_ASYNC16(sb + (OQ + r * 196 + c * 4) * 4,
                       Qf + (brow + j0 + r) * (size_t)DMODEL + h * 192 + c * 4);
        }
    } else {
        if (tid < 64)
            CP_ASYNC16(sb + (OQ + tid * 12) * 4,
                       Qh + (brow + j0 + tid) * (size_t)32 + h * 8);
        // zero pad cols 4..7 of Q, K0, K1 (fp16 k16 upper half)
#pragma unroll
        for (int i = 0; i < 3; ++i) {
            const int idx = tid + i * 256;
            const int arr = idx >> 8, rem = idx & 255;
            const int r = rem >> 2, c = 4 + (rem & 3);
            const int base = (arr == 0) ? OQ : ((arr == 1) ? OK0 : OK1);
            sm[base + r * 12 + c] = 0;
        }
    }
    // init running stats + query mask
    if (tid < 64) {
        fsm[OMX + tid] = -1e30f;
        fsm[OLX + tid] = 0.f;
    }
    const int mj0 = mask[brow + j0 + r0];
    const int mj1 = mask[brow + j0 + r1];

    auto load_tile = [&](int kt, int bufsel) {
        const int i0 = kt * 64;
        const int OK = bufsel ? OK1 : OK0, OV = bufsel ? OV1 : OV0;
        if (PAM) {
#pragma unroll
            for (int i = 0; i < 12; ++i) {
                const int idx = tid + i * 256;
                const int r = idx / 48, c = idx % 48;
                CP_ASYNC16(sb + (OK + r * 196 + c * 4) * 4,
                           Kf + (brow + i0 + r) * (size_t)DMODEL + h * 192 + c * 4);
            }
        } else {
            if (tid < 64)
                CP_ASYNC16(sb + (OK + tid * 12) * 4,
                           Kh + (brow + i0 + tid) * (size_t)32 + h * 8);
        }
#pragma unroll
        for (int i = 0; i < 6; ++i) {
            const int idx = tid + i * 256;
            const int r = idx >> 3, c = idx & 7;
            CP_ASYNC16(sb + (OV + r * 36 + c * 4) * 4,
                       Vt + ((size_t)bh * 192 + r) * 512 + kt * 32 + c * 4);
        }
        if (tid < 64)
            CP_ASYNC4(sb + (OMI + (kt & 1) * 64 + tid) * 4, mask + brow + i0 + tid);
    };
    load_tile(0, 0);
    CP_COMMIT();

    float acc[12][4];
#pragma unroll
    for (int n2 = 0; n2 < 12; ++n2)
#pragma unroll
        for (int e = 0; e < 4; ++e) acc[n2][e] = 0.f;

    for (int kt = 0; kt < 16; ++kt) {
        CP_WAIT0();
        __syncthreads();                              // (a) tile ready, prev PV done
        if (kt + 1 < 16) load_tile(kt + 1, (kt + 1) & 1);
        CP_COMMIT();
        const int OK = (kt & 1) ? OK1 : OK0;
        const int OV = (kt & 1) ? OV1 : OV0;

        // ---- S = Q K^T ----
        float s[4][4];
#pragma unroll
        for (int nt = 0; nt < 4; ++nt)
#pragma unroll
            for (int e = 0; e < 4; ++e) s[nt][e] = 0.f;
        if (PAM) {
#pragma unroll
            for (int ck = 0; ck < 24; ++ck) {
                uint32_t a[4];
                a[0] = sm[OQ + r0 * 196 + ck * 8 + t];
                a[1] = sm[OQ + r1 * 196 + ck * 8 + t];
                a[2] = sm[OQ + r0 * 196 + ck * 8 + t + 4];
                a[3] = sm[OQ + r1 * 196 + ck * 8 + t + 4];
#pragma unroll
                for (int nt = 0; nt < 4; ++nt) {
                    const int iw = nw * 32 + nt * 8 + g;
                    uint32_t bb[2];
                    bb[0] = sm[OK + iw * 196 + ck * 8 + t];
                    bb[1] = sm[OK + iw * 196 + ck * 8 + t + 4];
                    mma_tf32(s[nt], a, bb);
                }
            }
        } else {
            const uint32_t a0 = sm[OQ + r0 * 12 + t];
            const uint32_t a1 = sm[OQ + r1 * 12 + t];
            const uint32_t a2 = sm[OQ + r0 * 12 + t + 4];
            const uint32_t a3 = sm[OQ + r1 * 12 + t + 4];
#pragma unroll
            for (int nt = 0; nt < 4; ++nt) {
                const int iw = nw * 32 + nt * 8 + g;
                const uint32_t b0 = sm[OK + iw * 12 + t];
                const uint32_t b1 = sm[OK + iw * 12 + t + 4];
                mma_f16(s[nt], a0, a1, a2, a3, b0, b1);
            }
        }

        // ---- mask + scale + row max (warp-local over 32-i slice) ----
        const int obMI = OMI + (kt & 1) * 64;
        float vv[4][4];
        float m0 = -1e30f, m1 = -1e30f;
#pragma unroll
        for (int nt = 0; nt < 4; ++nt) {
            const int ii = nw * 32 + nt * 8 + 2 * t;
            const int mi0 = ism[obMI + ii], mi1 = ism[obMI + ii + 1];
            vv[nt][0] = (mj0 && mi0) ? s[nt][0] * scale : -1e7f;
            vv[nt][1] = (mj0 && mi1) ? s[nt][1] * scale : -1e7f;
            vv[nt][2] = (mj1 && mi0) ? s[nt][2] * scale : -1e7f;
            vv[nt][3] = (mj1 && mi1) ? s[nt][3] * scale : -1e7f;
            m0 = fmaxf(m0, fmaxf(vv[nt][0], vv[nt][1]));
            m1 = fmaxf(m1, fmaxf(vv[nt][2], vv[nt][3]));
        }
        m0 = fmaxf(m0, __shfl_xor_sync(0xffffffffu, m0, 1));
        m0 = fmaxf(m0, __shfl_xor_sync(0xffffffffu, m0, 2));
        m1 = fmaxf(m1, __shfl_xor_sync(0xffffffffu, m1, 1));
        m1 = fmaxf(m1, __shfl_xor_sync(0xffffffffu, m1, 2));
        if (t == 0) {
            fsm[ORM + nw * 64 + r0] = m0;
            fsm[ORM + nw * 64 + r1] = m1;
        }
        __syncthreads();                              // (b)

        // per-thread combine (no broadcast phase)
        const float mr0 = fmaxf(fsm[ORM + r0], fsm[ORM + 64 + r0]);
        const float mr1 = fmaxf(fsm[ORM + r1], fsm[ORM + 64 + r1]);
        const float mo0 = fsm[OMX + (kt & 1) * 64 + r0];
        const float mo1 = fsm[OMX + (kt & 1) * 64 + r1];
        const float mn0 = fmaxf(mo0, mr0), mn1 = fmaxf(mo1, mr1);
        const float c0f = __expf(mo0 - mn0), c1f = __expf(mo1 - mn1);
        if (nw == 0 && t == 0) {
            fsm[OMX + ((kt + 1) & 1) * 64 + r0] = mn0;
            fsm[OMX + ((kt + 1) & 1) * 64 + r1] = mn1;
        }

        // ---- exp, pack P, partial row sums ----
        float l0 = 0.f, l1 = 0.f;
#pragma unroll
        for (int nt = 0; nt < 4; ++nt) {
            const float p00 = __expf(vv[nt][0] - mn0);
            const float p01 = __expf(vv[nt][1] - mn0);
            const float p10 = __expf(vv[nt][2] - mn1);
            const float p11 = __expf(vv[nt][3] - mn1);
            l0 += p00 + p01;
            l1 += p10 + p11;
            sm[OP + r0 * 36 + nw * 16 + nt * 4 + t] = pack2h(p00, p01);
            sm[OP + r1 * 36 + nw * 16 + nt * 4 + t] = pack2h(p10, p11);
        }
        l0 += __shfl_xor_sync(0xffffffffu, l0, 1);
        l0 += __shfl_xor_sync(0xffffffffu, l0, 2);
        l1 += __shfl_xor_sync(0xffffffffu, l1, 1);
        l1 += __shfl_xor_sync(0xffffffffu, l1, 2);
        if (t == 0) {
            fsm[ORS + nw * 64 + r0] = l0;
            fsm[ORS + nw * 64 + r1] = l1;
        }
        __syncthreads();                              // (c)
        if (nw == 0 && t == 0) {
            fsm[OLX + ((kt + 1) & 1) * 64 + r0]
                = fsm[OLX + (kt & 1) * 64 + r0] * c0f + fsm[ORS + r0] + fsm[ORS + 64 + r0];
            fsm[OLX + ((kt + 1) & 1) * 64 + r1]
                = fsm[OLX + (kt & 1) * 64 + r1] * c1f + fsm[ORS + r1] + fsm[ORS + 64 + r1];
        }

        // ---- O = O*corr + P V ----
#pragma unroll
        for (int n2 = 0; n2 < 12; ++n2) {
            acc[n2][0] *= c0f; acc[n2][1] *= c0f;
            acc[n2][2] *= c1f; acc[n2][3] *= c1f;
        }
#pragma unroll
        for (int ck = 0; ck < 4; ++ck) {
            const uint32_t pa0 = sm[OP + r0 * 36 + ck * 8 + t];
            const uint32_t pa1 = sm[OP + r1 * 36 + ck * 8 + t];
            const uint32_t pa2 = sm[OP + r0 * 36 + ck * 8 + t + 4];
            const uint32_t pa3 = sm[OP + r1 * 36 + ck * 8 + t + 4];
#pragma unroll
            for (int n2 = 0; n2 < 12; ++n2) {
                const int d0 = nw * 96 + n2 * 8 + g;
                const uint32_t b0 = sm[OV + d0 * 36 + ck * 8 + t];
                const uint32_t b1 = sm[OV + d0 * 36 + ck * 8 + t + 4];
                mma_f16(acc[n2], pa0, pa1, pa2, pa3, b0, b1);
            }
        }
    }
    __syncthreads();   // final LX visible

    const float inv0 = 1.f / fsm[OLX + r0];   // parity (15+1)&1 == 0
    const float inv1 = 1.f / fsm[OLX + r1];
#pragma unroll
    for (int n2 = 0; n2 < 12; ++n2) {
        const int col = nw * 96 + n2 * 8 + 2 * t;
        float2 o0, o1;
        o0.x = rna(acc[n2][0] * inv0); o0.y = rna(acc[n2][1] * inv0);
        o1.x = rna(acc[n2][2] * inv1); o1.y = rna(acc[n2][3] * inv1);
        *(float2*)(Og + (brow + j0 + r0) * (size_t)DMODEL + h * DV + col) = o0;
        *(float2*)(Og + (brow + j0 + r1) * (size_t)DMODEL + h * DV + col) = o1;
    }
}

static int flash_smem_bytes(bool pam) {
    const int ldk = pam ? 196 : 12;
    const int u = 64 * ldk * 3 + 192 * 36 * 2 + 64 * 36 + 128 * 5;
    return u * 4;
}

// ---------------- tf32 GEMM, cp.async double-buffered + bias + ReLU ----------
// C[m][n] = relu( sum_k A(k)[m][k] * WT[n][k] + bias[n] ); operands pre-rounded.
__global__ __launch_bounds__(256, 2)
void gemm_cp(const float* __restrict__ A0, const float* __restrict__ A1,
             const float* __restrict__ WT, int ldw, int nk,
             const float* __restrict__ bias, float* __restrict__ C,
             int round_out)
{
    extern __shared__ __align__(16) uint32_t gsm[];   // sA[2][4608] sB[2][4608]
    const uint32_t sbase = smem_u32(gsm);

    const int tid  = threadIdx.x;
    const int wid  = tid >> 5, lane = tid & 31;
    const int g    = lane >> 2, t = lane & 3;
    const int mw   = wid >> 1;
    const int nw   = wid & 1;
    const int n0   = blockIdx.x * 128;
    const int m0   = blockIdx.y * 128;

    auto issue = [&](int kc, int st) {
        const int kb = kc * 32;
        const float* Ag = (kb < 768) ? (A0 + (size_t)m0 * 768 + kb)
                                     : (A1 + (size_t)m0 * 768 + (kb - 768));
        const float* Bg = WT + (size_t)n0 * ldw + kb;
#pragma unroll
        for (int i = 0; i < 4; ++i) {
            const int idx = tid + i * 256;
            const int r = idx >> 3, c = idx & 7;
            CP_ASYNC16(sbase + (st * 4608 + r * 36 + c * 4) * 4,
                       Ag + (size_t)r * 768 + c * 4);
            CP_ASYNC16(sbase + (9216 + st * 4608 + r * 36 + c * 4) * 4,
                       Bg + (size_t)r * ldw + c * 4);
        }
    };

    float acc[2][8][4];
#pragma unroll
    for (int mt = 0; mt < 2; ++mt)
#pragma unroll
        for (int nt = 0; nt < 8; ++nt)
#pragma unroll
            for (int e = 0; e < 4; ++e) acc[mt][nt][e] = 0.f;

    issue(0, 0);
    CP_COMMIT();

    for (int kc = 0; kc < nk; ++kc) {
        if (kc + 1 < nk) {
            issue(kc + 1, (kc + 1) & 1);
            CP_COMMIT();
            CP_WAIT1();
        } else {
            CP_WAIT0();
        }
        __syncthreads();

        const uint32_t* sA = gsm + (kc & 1) * 4608;
        const uint32_t* sB = gsm + 9216 + (kc & 1) * 4608;
#pragma unroll
        for (int kk = 0; kk < 32; kk += 8) {
            uint32_t a[2][4];
#pragma unroll
            for (int mt = 0; mt < 2; ++mt) {
                const int mb = mw * 32 + mt * 16;
                a[mt][0] = sA[(mb + g)     * 36 + kk + t];
                a[mt][1] = sA[(mb + g + 8) * 36 + kk + t];
                a[mt][2] = sA[(mb + g)     * 36 + kk + t + 4];
                a[mt][3] = sA[(mb + g + 8) * 36 + kk + t + 4];
            }
            uint32_t b[8][2];
#pragma unroll
            for (int nt = 0; nt < 8; ++nt) {
                const int cn = nw * 64 + nt * 8 + g;
                b[nt][0] = sB[cn * 36 + kk + t];
                b[nt][1] = sB[cn * 36 + kk + t + 4];
            }
#pragma unroll
            for (int mt = 0; mt < 2; ++mt)
#pragma unroll
                for (int nt = 0; nt < 8; ++nt)
                    mma_tf32(acc[mt][nt], a[mt], b[nt]);
        }
        __syncthreads();
    }

#pragma unroll
    for (int mt = 0; mt < 2; ++mt) {
        const int r0 = m0 + mw * 32 + mt * 16 + g;
#pragma unroll
        for (int nt = 0; nt < 8; ++nt) {
            const int col = n0 + nw * 64 + nt * 8 + 2 * t;
            const float b0 = __ldg(bias + col), b1 = __ldg(bias + col + 1);
            float2 o0, o1;
            o0.x = fmaxf(acc[mt][nt][0] + b0, 0.f);
            o0.y = fmaxf(acc[mt][nt][1] + b1, 0.f);
            o1.x = fmaxf(acc[mt][nt][2] + b0, 0.f);
            o1.y = fmaxf(acc[mt][nt][3] + b1, 0.f);
            if (round_out) {
                o0.x = rna(o0.x); o0.y = rna(o0.y);
                o1.x = rna(o1.x); o1.y = rna(o1.y);
            }
            *(float2*)(C + (size_t)r0 * 768 + col)       = o0;
            *(float2*)(C + (size_t)(r0 + 8) * 768 + col) = o1;
        }
    }
}

// ---------------- launch ------------------------------------------------------
extern "C" void kernel_launch(void* const* d_in, const int* in_sizes, int n_in,
                              void* d_out, int out_size)
{
    const float* x    = (const float*)d_in[0];
    const int*   mask = (const int*)  d_in[1];
    const float* pos  = (const float*)d_in[2];
    const float* Wq   = (const float*)d_in[3];
    const float* bq   = (const float*)d_in[4];
    const float* Wk   = (const float*)d_in[5];
    const float* bk   = (const float*)d_in[6];
    const float* Wpam = (const float*)d_in[7];
    const float* bpam = (const float*)d_in[8];
    const float* Wm   = (const float*)d_in[9];
    const float* bm   = (const float*)d_in[10];
    float* out = (float*)d_out;

    __half *gqh, *gkh;
    float *gposr, *gatt, *gpam, *gposp, *gwpt, *gwmt;
    uint32_t* gvt;
    cudaGetSymbolAddress((void**)&gqh,   g_qh);
    cudaGetSymbolAddress((void**)&gkh,   g_kh);
    cudaGetSymbolAddress((void**)&gposr, g_posr);
    cudaGetSymbolAddress((void**)&gvt,   g_vt);
    cudaGetSymbolAddress((void**)&gatt,  g_att);
    cudaGetSymbolAddress((void**)&gpam,  g_pam);
    cudaGetSymbolAddress((void**)&gposp, g_posp);
    cudaGetSymbolAddress((void**)&gwpt,  g_wpt);
    cudaGetSymbolAddress((void**)&gwmt,  g_wmt);

    const int smem_sam = flash_smem_bytes(false);   //  76,288 B
    const int smem_pam = flash_smem_bytes(true);    // 217,600 B
    const int smem_gemm = 18432 * 4;                //  73,728 B
    cudaFuncSetAttribute(flash2<false>, cudaFuncAttributeMaxDynamicSharedMemorySize, smem_sam);
    cudaFuncSetAttribute(flash2<true>,  cudaFuncAttributeMaxDynamicSharedMemorySize, smem_pam);
    cudaFuncSetAttribute(gemm_cp,       cudaFuncAttributeMaxDynamicSharedMemorySize, smem_gemm);

    const float sc_sam = 1.f / powf(8.f,   0.25f);
    const float sc_pam = 1.f / powf(192.f, 0.25f);

    // 0) operand prep
    prep_pos<<<BS * DMODEL / 1024, 256>>>(pos, gposr);
    prep_vt<<<dim3(16, 24, NB), 256>>>(x, gvt);
    transpose_k<<<dim3(24, 24), 256>>>(Wpam, gwpt, 768, 768);
    transpose_k<<<dim3(24, 48), 256>>>(Wm,   gwmt, 1536, 768);

    // 1) q/k projections (+ReLU) -> fp16
    qk_proj<<<1024, 256>>>(x, Wq, bq, Wk, bk, gqh, gkh);

    // 2) SAM attention (transposed-flash: Qflash = k, Kflash = q)
    flash2<false><<<dim3(16, NH, NB), 256, smem_sam>>>(
        nullptr, nullptr, gkh, gqh, gvt, mask, gatt, sc_sam);

    // 3) PAM attention: Q = K = position (tf32 QK^T)
    flash2<true><<<dim3(16, NH, NB), 256, smem_pam>>>(
        gposr, gposr, nullptr, nullptr, gvt, mask, gpam, sc_pam);

    // 4) pos_proj = relu(pam_out @ Wpam + bpam)
    gemm_cp<<<dim3(6, 64), 256, smem_gemm>>>(gpam, nullptr, gwpt, 768, 24, bpam, gposp, 1);

    // 5) out = relu(att @ Wm_top + pos_proj @ Wm_bot + bm)
    gemm_cp<<<dim3(6, 64), 256, smem_gemm>>>(gatt, gposp, gwmt, 1536, 48, bm, out, 0);
}

// round 15
// speedup vs baseline: 1.0018x; 1.0018x over previous
#include <cuda_runtime.h>
#include <cuda_fp16.h>
#include <math.h>
#include <stdint.h>

#define BS   8192           // B*S
#define SEQ  1024
#define NB   8
#define NH   4
#define DMODEL 768
#define DV   192            // per-head V dim

// ---------------- scratch (static device memory; no allocations) -------------
__device__ __half   g_qh[BS * 32];
__device__ __half   g_kh[BS * 32];
__device__ float    g_posr[BS * DMODEL];              // tf32-rounded position
__device__ uint32_t g_vt[NB * NH * 192 * 512];        // V^T half2: [bh][d][i/2]
__device__ float    g_att[BS * DMODEL];
__device__ float    g_pam[BS * DMODEL];
__device__ float    g_posp[BS * DMODEL];
__device__ float    g_wpt[DMODEL * DMODEL];           // Wpam^T (tf32-rounded)
__device__ float    g_wmt[DMODEL * 2 * DMODEL];       // Wm^T   (tf32-rounded)

// ---------------- helpers ----------------------------------------------------
__device__ __forceinline__ uint32_t smem_u32(const void* p) {
    uint32_t a;
    asm("{ .reg .u64 t; cvta.to.shared.u64 t, %1; cvt.u32.u64 %0, t; }"
        : "=r"(a) : "l"(p));
    return a;
}
__device__ __forceinline__ float rna(float f) {
    uint32_t r;
    asm("cvt.rna.tf32.f32 %0, %1;" : "=r"(r) : "f"(f));
    return __uint_as_float(r);
}
__device__ __forceinline__ void mma_tf32(float c[4], const uint32_t a[4],
                                         const uint32_t b[2]) {
    asm volatile("mma.sync.aligned.m16n8k8.row.col.f32.tf32.tf32.f32 "
                 "{%0,%1,%2,%3}, {%4,%5,%6,%7}, {%8,%9}, {%0,%1,%2,%3};"
                 : "+f"(c[0]), "+f"(c[1]), "+f"(c[2]), "+f"(c[3])
                 : "r"(a[0]), "r"(a[1]), "r"(a[2]), "r"(a[3]),
                   "r"(b[0]), "r"(b[1]));
}
__device__ __forceinline__ void mma_f16(float c[4],
                                        uint32_t a0, uint32_t a1,
                                        uint32_t a2, uint32_t a3,
                                        uint32_t b0, uint32_t b1) {
    asm volatile("mma.sync.aligned.m16n8k16.row.col.f32.f16.f16.f32 "
                 "{%0,%1,%2,%3}, {%4,%5,%6,%7}, {%8,%9}, {%0,%1,%2,%3};"
                 : "+f"(c[0]), "+f"(c[1]), "+f"(c[2]), "+f"(c[3])
                 : "r"(a0), "r"(a1), "r"(a2), "r"(a3), "r"(b0), "r"(b1));
}
__device__ __forceinline__ uint32_t pack2h(float a, float b) {
    __half ha = __float2half_rn(a), hb = __float2half_rn(b);
    return (uint32_t)__half_as_ushort(ha) | ((uint32_t)__half_as_ushort(hb) << 16);
}
#define CP_ASYNC16(saddr, gptr) \
    asm volatile("cp.async.cg.shared.global [%0], [%1], 16;" \
                 :: "r"(saddr), "l"(gptr))
#define CP_ASYNC4(saddr, gptr) \
    asm volatile("cp.async.ca.shared.global [%0], [%1], 4;" \
                 :: "r"(saddr), "l"(gptr))
#define CP_COMMIT() asm volatile("cp.async.commit_group;")
#define CP_WAIT0()  asm volatile("cp.async.wait_group 0;")
#define CP_WAIT1()  asm volatile("cp.async.wait_group 1;")

// ---------------- prep kernels ------------------------------------------------
__global__ __launch_bounds__(256)
void prep_pos(const float* __restrict__ pos, float* __restrict__ out)
{
    const int idx = blockIdx.x * 256 + threadIdx.x;
    const float4 v = *(const float4*)(pos + (size_t)idx * 4);
    float4 o;
    o.x = rna(v.x); o.y = rna(v.y); o.z = rna(v.z); o.w = rna(v.w);
    *(float4*)(out + (size_t)idx * 4) = o;
}

// V^T prep: g_vt[(b*NH+h)*192+d][m] = half2(x[b][2m][h*192+d], x[b][2m+1][..])
__global__ __launch_bounds__(256)
void prep_vt(const float* __restrict__ x, uint32_t* __restrict__ vt)
{
    __shared__ float t[64][33];
    const int s0 = blockIdx.x * 64, c0 = blockIdx.y * 32, b = blockIdx.z;
    const int tid = threadIdx.x;
#pragma unroll
    for (int i = 0; i < 8; ++i) {
        const int idx = tid + i * 256;
        const int r = idx >> 5, cc = idx & 31;
        t[r][cc] = x[((size_t)b * SEQ + s0 + r) * DMODEL + c0 + cc];
    }
    __syncthreads();
#pragma unroll
    for (int i = 0; i < 4; ++i) {
        const int idx = tid + i * 256;
        const int cc = idx >> 5, m = idx & 31;
        const int c = c0 + cc, h = c / 192, d = c % 192;
        vt[((size_t)(b * NH + h) * 192 + d) * 512 + s0 / 2 + m]
            = pack2h(t[2 * m][cc], t[2 * m + 1][cc]);
    }
}

// weight transpose W[K][N] -> WT[N][K], tf32-rounded
__global__ __launch_bounds__(256)
void transpose_k(const float* __restrict__ W, float* __restrict__ WT, int K, int N)
{
    __shared__ float t[32][33];
    const int k0 = blockIdx.y * 32, n0 = blockIdx.x * 32;
    const int tx = threadIdx.x & 31, ty = threadIdx.x >> 5;
#pragma unroll
    for (int r = ty; r < 32; r += 8)
        t[r][tx] = W[(size_t)(k0 + r) * N + n0 + tx];
    __syncthreads();
#pragma unroll
    for (int r = ty; r < 32; r += 8)
        WT[(size_t)(n0 + r) * K + k0 + tx] = rna(t[tx][r]);
}

// ---------------- q/k projection + ReLU -> fp16 -------------------------------
__global__ __launch_bounds__(256)
void qk_proj(const float* __restrict__ x,
             const float* __restrict__ Wq, const float* __restrict__ bq,
             const float* __restrict__ Wk, const float* __restrict__ bk,
             __half* __restrict__ q, __half* __restrict__ k)
{
    const int row  = (blockIdx.x * blockDim.x + threadIdx.x) >> 5;
    const int lane = threadIdx.x & 31;
    if (row >= BS) return;
    const float* xr = x + (size_t)row * DMODEL;
    float aq = bq[lane];
    float ak = bk[lane];
#pragma unroll 8
    for (int d = 0; d < DMODEL; ++d) {
        const float xv = __ldg(xr + d);
        aq = fmaf(xv, __ldg(Wq + d * 32 + lane), aq);
        ak = fmaf(xv, __ldg(Wk + d * 32 + lane), ak);
    }
    q[(size_t)row * 32 + lane] = __float2half_rn(fmaxf(aq, 0.f));
    k[(size_t)row * 32 + lane] = __float2half_rn(fmaxf(ak, 0.f));
}

// ---------------- flash attention, cp.async pipelined --------------------------
// out[j] = sum_i softmax_i( Q[j]·K[i]*scale, masked ) * V[i]   (transpose trick)
// PAM=true : Q/K = tf32 fp32 rows of 192 (g_posr); QK^T via m16n8k8 tf32.
// PAM=false: Q/K = fp16 rows of 8 (g_kh/g_qh);    QK^T via one m16n8k16 fp16.
// PV: fp16 m16n8k16 from pre-transposed g_vt. 3 barriers/iter, double-buffered.
template<bool PAM>
__global__ __launch_bounds__(256)
void flash2(const float* __restrict__ Qf, const float* __restrict__ Kf,
            const __half* __restrict__ Qh, const __half* __restrict__ Kh,
            const uint32_t* __restrict__ Vt, const int* __restrict__ mask,
            float* __restrict__ Og, float scale)
{
    constexpr int LDK = PAM ? 196 : 12;       // u32 row stride (=4 mod 32)
    constexpr int OQ  = 0;
    constexpr int OK0 = OQ  + 64 * LDK;
    constexpr int OK1 = OK0 + 64 * LDK;
    constexpr int OV0 = OK1 + 64 * LDK;
    constexpr int OV1 = OV0 + 192 * 36;
    constexpr int OP  = OV1 + 192 * 36;
    constexpr int ORM = OP  + 64 * 36;
    constexpr int ORS = ORM + 128;
    constexpr int OMX = ORS + 128;            // [2][64]
    constexpr int OLX = OMX + 128;            // [2][64]
    constexpr int OMI = OLX + 128;            // [2][64] int

    extern __shared__ __align__(16) uint32_t sm[];
    float* fsm = (float*)sm;
    int*   ism = (int*)sm;
    const uint32_t sb = smem_u32(sm);

    const int tid = threadIdx.x;
    const int wid = tid >> 5, lane = tid & 31;
    const int g = lane >> 2, t = lane & 3;
    const int mw = wid >> 1, nw = wid & 1;
    const int r0 = mw * 16 + g, r1 = r0 + 8;
    const int qt = blockIdx.x, h = blockIdx.y, b = blockIdx.z;
    const int j0 = qt * 64;
    const long brow = (long)b * SEQ;
    const int bh = b * NH + h;

    // --- issue Q tile loads ---
    if (PAM) {
#pragma unroll
        for (int i = 0; i < 12; ++i) {
            const int idx = tid + i * 256;
            const int r = idx / 48, c = idx % 48;
            CP_ASYNC16(sb + (OQ + r * 196 + c * 4) * 4,
                       Qf + (brow + j0 + r) * (size_t)DMODEL + h * 192 + c * 4);
        }
    } else {
        if (tid < 64)
            CP_ASYNC16(sb + (OQ + tid * 12) * 4,
                       Qh + (brow + j0 + tid) * (size_t)32 + h * 8);
        // zero pad cols 4..7 of Q, K0, K1 (fp16 k16 upper half)
#pragma unroll
        for (int i = 0; i < 3; ++i) {
            const int idx = tid + i * 256;
            const int arr = idx >> 8, rem = idx & 255;
            const int r = rem >> 2, c = 4 + (rem & 3);
            const int base = (arr == 0) ? OQ : ((arr == 1) ? OK0 : OK1);
            sm[base + r * 12 + c] = 0;
        }
    }
    // init running stats + query mask
    if (tid < 64) {
        fsm[OMX + tid] = -1e30f;
        fsm[OLX + tid] = 0.f;
    }
    const int mj0 = mask[brow + j0 + r0];
    const int mj1 = mask[brow + j0 + r1];

    auto load_tile = [&](int kt, int bufsel) {
        const int i0 = kt * 64;
        const int OK = bufsel ? OK1 : OK0, OV = bufsel ? OV1 : OV0;
        if (PAM) {
#pragma unroll
            for (int i = 0; i < 12; ++i) {
                const int idx = tid + i * 256;
                const int r = idx / 48, c = idx % 48;
                CP_ASYNC16(sb + (OK + r * 196 + c * 4) * 4,
                           Kf + (brow + i0 + r) * (size_t)DMODEL + h * 192 + c * 4);
            }
        } else {
            if (tid < 64)
                CP_ASYNC16(sb + (OK + tid * 12) * 4,
                           Kh + (brow + i0 + tid) * (size_t)32 + h * 8);
        }
#pragma unroll
        for (int i = 0; i < 6; ++i) {
            const int idx = tid + i * 256;
            const int r = idx >> 3, c = idx & 7;
            CP_ASYNC16(sb + (OV + r * 36 + c * 4) * 4,
                       Vt + ((size_t)bh * 192 + r) * 512 + kt * 32 + c * 4);
        }
        if (tid < 64)
            CP_ASYNC4(sb + (OMI + (kt & 1) * 64 + tid) * 4, mask + brow + i0 + tid);
    };
    load_tile(0, 0);
    CP_COMMIT();

    float acc[12][4];
#pragma unroll
    for (int n2 = 0; n2 < 12; ++n2)
#pragma unroll
        for (int e = 0; e < 4; ++e) acc[n2][e] = 0.f;

    for (int kt = 0; kt < 16; ++kt) {
        CP_WAIT0();
        __syncthreads();                              // (a) tile ready, prev PV done
        if (kt + 1 < 16) load_tile(kt + 1, (kt + 1) & 1);
        CP_COMMIT();
        const int OK = (kt & 1) ? OK1 : OK0;
        const int OV = (kt & 1) ? OV1 : OV0;

        // ---- S = Q K^T ----
        float s[4][4];
#pragma unroll
        for (int nt = 0; nt < 4; ++nt)
#pragma unroll
            for (int e = 0; e < 4; ++e) s[nt][e] = 0.f;
        if (PAM) {
#pragma unroll
            for (int ck = 0; ck < 24; ++ck) {
                uint32_t a[4];
                a[0] = sm[OQ + r0 * 196 + ck * 8 + t];
                a[1] = sm[OQ + r1 * 196 + ck * 8 + t];
                a[2] = sm[OQ + r0 * 196 + ck * 8 + t + 4];
                a[3] = sm[OQ + r1 * 196 + ck * 8 + t + 4];
#pragma unroll
                for (int nt = 0; nt < 4; ++nt) {
                    const int iw = nw * 32 + nt * 8 + g;
                    uint32_t bb[2];
                    bb[0] = sm[OK + iw * 196 + ck * 8 + t];
                    bb[1] = sm[OK + iw * 196 + ck * 8 + t + 4];
                    mma_tf32(s[nt], a, bb);
                }
            }
        } else {
            const uint32_t a0 = sm[OQ + r0 * 12 + t];
            const uint32_t a1 = sm[OQ + r1 * 12 + t];
            const uint32_t a2 = sm[OQ + r0 * 12 + t + 4];
            const uint32_t a3 = sm[OQ + r1 * 12 + t + 4];
#pragma unroll
            for (int nt = 0; nt < 4; ++nt) {
                const int iw = nw * 32 + nt * 8 + g;
                const uint32_t b0 = sm[OK + iw * 12 + t];
                const uint32_t b1 = sm[OK + iw * 12 + t + 4];
                mma_f16(s[nt], a0, a1, a2, a3, b0, b1);
            }
        }

        // ---- mask + scale + row max (warp-local over 32-i slice) ----
        const int obMI = OMI + (kt & 1) * 64;
        float vv[4][4];
        float m0 = -1e30f, m1 = -1e30f;
#pragma unroll
        for (int nt = 0; nt < 4; ++nt) {
            const int ii = nw * 32 + nt * 8 + 2 * t;
            const int mi0 = ism[obMI + ii], mi1 = ism[obMI + ii + 1];
            vv[nt][0] = (mj0 && mi0) ? s[nt][0] * scale : -1e7f;
            vv[nt][1] = (mj0 && mi1) ? s[nt][1] * scale : -1e7f;
            vv[nt][2] = (mj1 && mi0) ? s[nt][2] * scale : -1e7f;
            vv[nt][3] = (mj1 && mi1) ? s[nt][3] * scale : -1e7f;
            m0 = fmaxf(m0, fmaxf(vv[nt][0], vv[nt][1]));
            m1 = fmaxf(m1, fmaxf(vv[nt][2], vv[nt][3]));
        }
        m0 = fmaxf(m0, __shfl_xor_sync(0xffffffffu, m0, 1));
        m0 = fmaxf(m0, __shfl_xor_sync(0xffffffffu, m0, 2));
        m1 = fmaxf(m1, __shfl_xor_sync(0xffffffffu, m1, 1));
        m1 = fmaxf(m1, __shfl_xor_sync(0xffffffffu, m1, 2));
        if (t == 0) {
            fsm[ORM + nw * 64 + r0] = m0;
            fsm[ORM + nw * 64 + r1] = m1;
        }
        __syncthreads();                              // (b)

        // per-thread combine (no broadcast phase)
        const float mr0 = fmaxf(fsm[ORM + r0], fsm[ORM + 64 + r0]);
        const float mr1 = fmaxf(fsm[ORM + r1], fsm[ORM + 64 + r1]);
        const float mo0 = fsm[OMX + (kt & 1) * 64 + r0];
        const float mo1 = fsm[OMX + (kt & 1) * 64 + r1];
        const float mn0 = fmaxf(mo0, mr0), mn1 = fmaxf(mo1, mr1);
        const float c0f = __expf(mo0 - mn0), c1f = __expf(mo1 - mn1);
        if (nw == 0 && t == 0) {
            fsm[OMX + ((kt + 1) & 1) * 64 + r0] = mn0;
            fsm[OMX + ((kt + 1) & 1) * 64 + r1] = mn1;
        }

        // ---- exp, pack P, partial row sums ----
        float l0 = 0.f, l1 = 0.f;
#pragma unroll
        for (int nt = 0; nt < 4; ++nt) {
            const float p00 = __expf(vv[nt][0] - mn0);
            const float p01 = __expf(vv[nt][1] - mn0);
            const float p10 = __expf(vv[nt][2] - mn1);
            const float p11 = __expf(vv[nt][3] - mn1);
            l0 += p00 + p01;
            l1 += p10 + p11;
            sm[OP + r0 * 36 + nw * 16 + nt * 4 + t] = pack2h(p00, p01);
            sm[OP + r1 * 36 + nw * 16 + nt * 4 + t] = pack2h(p10, p11);
        }
        l0 += __shfl_xor_sync(0xffffffffu, l0, 1);
        l0 += __shfl_xor_sync(0xffffffffu, l0, 2);
        l1 += __shfl_xor_sync(0xffffffffu, l1, 1);
        l1 += __shfl_xor_sync(0xffffffffu, l1, 2);
        if (t == 0) {
            fsm[ORS + nw * 64 + r0] = l0;
            fsm[ORS + nw * 64 + r1] = l1;
        }
        __syncthreads();                              // (c)
        if (nw == 0 && t == 0) {
            fsm[OLX + ((kt + 1) & 1) * 64 + r0]
                = fsm[OLX + (kt & 1) * 64 + r0] * c0f + fsm[ORS + r0] + fsm[ORS + 64 + r0];
            fsm[OLX + ((kt + 1) & 1) * 64 + r1]
                = fsm[OLX + (kt & 1) * 64 + r1] * c1f + fsm[ORS + r1] + fsm[ORS + 64 + r1];
        }

        // ---- O = O*corr + P V ----
#pragma unroll
        for (int n2 = 0; n2 < 12; ++n2) {
            acc[n2][0] *= c0f; acc[n2][1] *= c0f;
            acc[n2][2] *= c1f; acc[n2][3] *= c1f;
        }
#pragma unroll
        for (int ck = 0; ck < 4; ++ck) {
            const uint32_t pa0 = sm[OP + r0 * 36 + ck * 8 + t];
            const uint32_t pa1 = sm[OP + r1 * 36 + ck * 8 + t];
            const uint32_t pa2 = sm[OP + r0 * 36 + ck * 8 + t + 4];
            const uint32_t pa3 = sm[OP + r1 * 36 + ck * 8 + t + 4];
#pragma unroll
            for (int n2 = 0; n2 < 12; ++n2) {
                const int d0 = nw * 96 + n2 * 8 + g;
                const uint32_t b0 = sm[OV + d0 * 36 + ck * 8 + t];
                const uint32_t b1 = sm[OV + d0 * 36 + ck * 8 + t + 4];
                mma_f16(acc[n2], pa0, pa1, pa2, pa3, b0, b1);
            }
        }
    }
    __syncthreads();   // final LX visible

    const float inv0 = 1.f / fsm[OLX + r0];   // parity (15+1)&1 == 0
    const float inv1 = 1.f / fsm[OLX + r1];
#pragma unroll
    for (int n2 = 0; n2 < 12; ++n2) {
        const int col = nw * 96 + n2 * 8 + 2 * t;
        float2 o0, o1;
        o0.x = rna(acc[n2][0] * inv0); o0.y = rna(acc[n2][1] * inv0);
        o1.x = rna(acc[n2][2] * inv1); o1.y = rna(acc[n2][3] * inv1);
        *(float2*)(Og + (brow + j0 + r0) * (size_t)DMODEL + h * DV + col) = o0;
        *(float2*)(Og + (brow + j0 + r1) * (size_t)DMODEL + h * DV + col) = o1;
    }
}

static int flash_smem_bytes(bool pam) {
    const int ldk = pam ? 196 : 12;
    const int u = 64 * ldk * 3 + 192 * 36 * 2 + 64 * 36 + 128 * 5;
    return u * 4;
}

// ---------------- tf32 GEMM, cp.async double-buffered + bias + ReLU ----------
// C[m][n] = relu( sum_k A(k)[m][k] * WT[n][k] + bias[n] ); operands pre-rounded.
__global__ __launch_bounds__(256, 2)
void gemm_cp(const float* __restrict__ A0, const float* __restrict__ A1,
             const float* __restrict__ WT, int ldw, int nk,
             const float* __restrict__ bias, float* __restrict__ C,
             int round_out)
{
    extern __shared__ __align__(16) uint32_t gsm[];   // sA[2][4608] sB[2][4608]
    const uint32_t sbase = smem_u32(gsm);

    const int tid  = threadIdx.x;
    const int wid  = tid >> 5, lane = tid & 31;
    const int g    = lane >> 2, t = lane & 3;
    const int mw   = wid >> 1;
    const int nw   = wid & 1;
    const int n0   = blockIdx.x * 128;
    const int m0   = blockIdx.y * 128;

    auto issue = [&](int kc, int st) {
        const int kb = kc * 32;
        const float* Ag = (kb < 768) ? (A0 + (size_t)m0 * 768 + kb)
                                     : (A1 + (size_t)m0 * 768 + (kb - 768));
        const float* Bg = WT + (size_t)n0 * ldw + kb;
#pragma unroll
        for (int i = 0; i < 4; ++i) {
            const int idx = tid + i * 256;
            const int r = idx >> 3, c = idx & 7;
            CP_ASYNC16(sbase + (st * 4608 + r * 36 + c * 4) * 4,
                       Ag + (size_t)r * 768 + c * 4);
            CP_ASYNC16(sbase + (9216 + st * 4608 + r * 36 + c * 4) * 4,
                       Bg + (size_t)r * ldw + c * 4);
        }
    };

    float acc[2][8][4];
#pragma unroll
    for (int mt = 0; mt < 2; ++mt)
#pragma unroll
        for (int nt = 0; nt < 8; ++nt)
#pragma unroll
            for (int e = 0; e < 4; ++e) acc[mt][nt][e] = 0.f;

    issue(0, 0);
    CP_COMMIT();

    for (int kc = 0; kc < nk; ++kc) {
        if (kc + 1 < nk) {
            issue(kc + 1, (kc + 1) & 1);
            CP_COMMIT();
            CP_WAIT1();
        } else {
            CP_WAIT0();
        }
        __syncthreads();

        const uint32_t* sA = gsm + (kc & 1) * 4608;
        const uint32_t* sB = gsm + 9216 + (kc & 1) * 4608;
#pragma unroll
        for (int kk = 0; kk < 32; kk += 8) {
            uint32_t a[2][4];
#pragma unroll
            for (int mt = 0; mt < 2; ++mt) {
                const int mb = mw * 32 + mt * 16;
                a[mt][0] = sA[(mb + g)     * 36 + kk + t];
                a[mt][1] = sA[(mb + g + 8) * 36 + kk + t];
                a[mt][2] = sA[(mb + g)     * 36 + kk + t + 4];
                a[mt][3] = sA[(mb + g + 8) * 36 + kk + t + 4];
            }
            uint32_t b[8][2];
#pragma unroll
            for (int nt = 0; nt < 8; ++nt) {
                const int cn = nw * 64 + nt * 8 + g;
                b[nt][0] = sB[cn * 36 + kk + t];
                b[nt][1] = sB[cn * 36 + kk + t + 4];
            }
#pragma unroll
            for (int mt = 0; mt < 2; ++mt)
#pragma unroll
                for (int nt = 0; nt < 8; ++nt)
                    mma_tf32(acc[mt][nt], a[mt], b[nt]);
        }
        __syncthreads();
    }

#pragma unroll
    for (int mt = 0; mt < 2; ++mt) {
        const int r0 = m0 + mw * 32 + mt * 16 + g;
#pragma unroll
        for (int nt = 0; nt < 8; ++nt) {
            const int col = n0 + nw * 64 + nt * 8 + 2 * t;
            const float b0 = __ldg(bias + col), b1 = __ldg(bias + col + 1);
            float2 o0, o1;
            o0.x = fmaxf(acc[mt][nt][0] + b0, 0.f);
            o0.y = fmaxf(acc[mt][nt][1] + b1, 0.f);
            o1.x = fmaxf(acc[mt][nt][2] + b0, 0.f);
            o1.y = fmaxf(acc[mt][nt][3] + b1, 0.f);
            if (round_out) {
                o0.x = rna(o0.x); o0.y = rna(o0.y);
                o1.x = rna(o1.x); o1.y = rna(o1.y);
            }
            *(float2*)(C + (size_t)r0 * 768 + col)       = o0;
            *(float2*)(C + (size_t)(r0 + 8) * 768 + col) = o1;
        }
    }
}

// ---------------- launch ------------------------------------------------------
extern "C" void kernel_launch(void* const* d_in, const int* in_sizes, int n_in,
                              void* d_out, int out_size)
{
    const float* x    = (const float*)d_in[0];
    const int*   mask = (const int*)  d_in[1];
    const float* pos  = (const float*)d_in[2];
    const float* Wq   = (const float*)d_in[3];
    const float* bq   = (const float*)d_in[4];
    const float* Wk   = (const float*)d_in[5];
    const float* bk   = (const float*)d_in[6];
    const float* Wpam = (const float*)d_in[7];
    const float* bpam = (const float*)d_in[8];
    const float* Wm   = (const float*)d_in[9];
    const float* bm   = (const float*)d_in[10];
    float* out = (float*)d_out;

    __half *gqh, *gkh;
    float *gposr, *gatt, *gpam, *gposp, *gwpt, *gwmt;
    uint32_t* gvt;
    cudaGetSymbolAddress((void**)&gqh,   g_qh);
    cudaGetSymbolAddress((void**)&gkh,   g_kh);
    cudaGetSymbolAddress((void**)&gposr, g_posr);
    cudaGetSymbolAddress((void**)&gvt,   g_vt);
    cudaGetSymbolAddress((void**)&gatt,  g_att);
    cudaGetSymbolAddress((void**)&gpam,  g_pam);
    cudaGetSymbolAddress((void**)&gposp, g_posp);
    cudaGetSymbolAddress((void**)&gwpt,  g_wpt);
    cudaGetSymbolAddress((void**)&gwmt,  g_wmt);

    const int smem_sam = flash_smem_bytes(false);   //  76,288 B
    const int smem_pam = flash_smem_bytes(true);    // 217,600 B
    const int smem_gemm = 18432 * 4;                //  73,728 B
    cudaFuncSetAttribute(flash2<false>, cudaFuncAttributeMaxDynamicSharedMemorySize, smem_sam);
    cudaFuncSetAttribute(flash2<true>,  cudaFuncAttributeMaxDynamicSharedMemorySize, smem_pam);
    cudaFuncSetAttribute(gemm_cp,       cudaFuncAttributeMaxDynamicSharedMemorySize, smem_gemm);

    const float sc_sam = 1.f / powf(8.f,   0.25f);
    const float sc_pam = 1.f / powf(192.f, 0.25f);

    // 0) operand prep
    prep_pos<<<BS * DMODEL / 1024, 256>>>(pos, gposr);
    prep_vt<<<dim3(16, 24, NB), 256>>>(x, gvt);
    transpose_k<<<dim3(24, 24), 256>>>(Wpam, gwpt, 768, 768);
    transpose_k<<<dim3(24, 48), 256>>>(Wm,   gwmt, 1536, 768);

    // 1) q/k projections (+ReLU) -> fp16
    qk_proj<<<1024, 256>>>(x, Wq, bq, Wk, bk, gqh, gkh);

    // 2) SAM attention (transposed-flash: Qflash = k, Kflash = q)
    flash2<false><<<dim3(16, NH, NB), 256, smem_sam>>>(
        nullptr, nullptr, gkh, gqh, gvt, mask, gatt, sc_sam);

    // 3) PAM attention: Q = K = position (tf32 QK^T)
    flash2<true><<<dim3(16, NH, NB), 256, smem_pam>>>(
        gposr, gposr, nullptr, nullptr, gvt, mask, gpam, sc_pam);

    // 4) pos_proj = relu(pam_out @ Wpam + bpam)
    gemm_cp<<<dim3(6, 64), 256, smem_gemm>>>(gpam, nullptr, gwpt, 768, 24, bpam, gposp, 1);

    // 5) out = relu(att @ Wm_top + pos_proj @ Wm_bot + bm)
    gemm_cp<<<dim3(6, 64), 256, smem_gemm>>>(gatt, gposp, gwmt, 1536, 48, bm, out, 0);
}